// round 14
// baseline (speedup 1.0000x reference)
#include <cuda_runtime.h>
#include <cuda_bf16.h>
#include <cuda_fp16.h>
#include <cstdint>

// Problem constants
#define BB 8
#define CC 128
#define OO 256
#define HH 96
#define WW 96
#define SS (HH*WW)          // 9216
#define KK 9                // 3x3 taps
#define CK (CC*KK)          // 1152
#define BSS (BB*SS)         // 73728
#define NCH 18              // K chunks of 64 channels (ch = tap*2 + half)

// ---------------- static device scratch (no allocs allowed) ----------------
__device__ __align__(16) __half g_xh[(size_t)BSS*CC];     // x NHWC fp16 (both gathers)
__device__ __align__(16) float4 g_mw[(size_t)KK*BSS];     // corner weights (tap-major)
__device__ __align__(16) int4   g_mi[(size_t)KK*BSS];     // corner indices (tap-major)
__device__ __align__(16) __half g_wh[(size_t)NCH*OO*64];  // fp16 main weights, swizzled
__device__ __align__(16) __half g_wom[(size_t)NCH*32*64]; // fp16 offset+mask weights, swizzled

// ---------------- helpers ----------------
__device__ __forceinline__ uint32_t smem_u32(const void* p) {
    uint32_t a;
    asm("{ .reg .u64 t; cvta.to.shared.u64 t, %1; cvt.u32.u64 %0, t; }" : "=r"(a) : "l"(p));
    return a;
}
// pack two fp32 -> f16x2 (lo in low half)
__device__ __forceinline__ uint32_t pkh2(float lo, float hi) {
    uint32_t r;
    asm("cvt.rn.f16x2.f32 %0, %1, %2;" : "=r"(r) : "f"(hi), "f"(lo));
    return r;
}
__device__ __forceinline__ void ldsm4(uint32_t* r, uint32_t addr) {
    asm volatile("ldmatrix.sync.aligned.m8n8.x4.shared.b16 {%0,%1,%2,%3}, [%4];"
                 : "=r"(r[0]), "=r"(r[1]), "=r"(r[2]), "=r"(r[3]) : "r"(addr));
}
__device__ __forceinline__ void mma16816h(float* c, const uint32_t* a, uint32_t b0, uint32_t b1) {
    asm volatile(
        "mma.sync.aligned.m16n8k16.row.col.f32.f16.f16.f32 "
        "{%0,%1,%2,%3}, {%4,%5,%6,%7}, {%8,%9}, {%0,%1,%2,%3};"
        : "+f"(c[0]), "+f"(c[1]), "+f"(c[2]), "+f"(c[3])
        : "r"(a[0]), "r"(a[1]), "r"(a[2]), "r"(a[3]), "r"(b0), "r"(b1));
}
__device__ __forceinline__ void cp16(uint32_t dst, const void* src) {
    asm volatile("cp.async.cg.shared.global [%0], [%1], 16;" :: "r"(dst), "l"(src));
}
// 16-byte cp.async with zero-fill when srcsize==0 (address must still be valid)
__device__ __forceinline__ void cp16z(uint32_t dst, const void* src, uint32_t srcsize) {
    asm volatile("cp.async.cg.shared.global [%0], [%1], 16, %2;"
                 :: "r"(dst), "l"(src), "r"(srcsize));
}

// ---------------- kernel 0a: NCHW fp32 -> NHWC fp16 ----------------
__global__ void transpose_x_kernel(const float* __restrict__ x) {
    __shared__ float tile[32][33];
    int s0 = blockIdx.x * 32;
    int c0 = blockIdx.y * 32;
    int b  = blockIdx.z;
    int tx = threadIdx.x, ty = threadIdx.y;
    #pragma unroll
    for (int i = 0; i < 4; i++) {
        int c = c0 + ty + i * 8;
        tile[ty + i * 8][tx] = x[((size_t)b * CC + c) * SS + s0 + tx];
    }
    __syncthreads();
    int tid = ty * 32 + tx;
    #pragma unroll
    for (int r = 0; r < 2; r++) {
        int idx = tid + r * 256;           // 0..511 over 32 s x 16 ch-pairs
        int sl = idx >> 4, pr = idx & 15;
        __half2 h = __floats2half2_rn(tile[2 * pr][sl], tile[2 * pr + 1][sl]);
        *(__half2*)(g_xh + ((size_t)b * SS + s0 + sl) * CC + c0 + 2 * pr) = h;
    }
}

// ---------------- kernel 0b: main weight -> fp16 swizzled chunk tiles ----------------
__global__ void wprep_kernel(const float* __restrict__ w) {
    int o  = blockIdx.x;        // 0..255
    int ch = blockIdx.y;        // 0..17
    int j  = threadIdx.x;       // 0..63
    int k  = ch >> 1, c = (ch & 1) * 64 + j;
    float v = w[(size_t)o * CK + (size_t)c * KK + k];
    int off = o * 128 + j * 2;
    int sw = off ^ ((o & 7) << 4);
    *(__half*)((char*)g_wh + (size_t)ch * 32768 + sw) = __float2half_rn(v);
}

// ---------------- kernel 0c: offset+mask weight -> fp16 swizzled tiles ----------------
// rows 0..17 = offset_w, 18..26 = mask_w, 27..31 = zero. Tile [32 rows][64 ch].
__global__ void owprep_kernel(const float* __restrict__ ow, const float* __restrict__ mw) {
    int o  = blockIdx.x;        // 0..31
    int ch = blockIdx.y;        // 0..17
    int j  = threadIdx.x;       // 0..63
    int k  = ch >> 1, c = (ch & 1) * 64 + j;
    float v = 0.f;
    if (o < 18)      v = ow[((size_t)o * CC + c) * KK + k];
    else if (o < 27) v = mw[((size_t)(o - 18) * CC + c) * KK + k];
    int off = o * 128 + j * 2;
    int sw = off ^ ((o & 7) << 4);
    *(__half*)((char*)g_wom + (size_t)ch * 4096 + sw) = __float2half_rn(v);
}

// ---------------- kernel 1: offset+mask conv as fp16 MMA + meta epilogue ----------------
// CTA: 128 px x 32 oc, 256 threads, 8 warps (4M x 2N). A built fully via cp.async im2col.
#define OSM_A    0          // 2 x 16384
#define OSM_B    32768      // 2 x 4096
#define OSM_YX   40960      // int[128]
#define OSM_EP   0          // epilogue staging reuses A
#define OSM_TOT  41472

__global__ __launch_bounds__(256) void offmask_mma_kernel(
    const float* __restrict__ ob, const float* __restrict__ mb)
{
    extern __shared__ char smem[];
    uint32_t sb = smem_u32(smem);
    int tid = threadIdx.x;
    int wid = tid >> 5;
    int lane = tid & 31;

    int tile = blockIdx.x;
    int b = tile / (SS / 128);
    int s0 = (tile - b * (SS / 128)) * 128;

    const __half* xh = g_xh + (size_t)b * SS * CC;
    int* s_yx = (int*)(smem + OSM_YX);

    // precompute per-px (y,x) once
    if (tid < 128) {
        int s = s0 + tid;
        s_yx[tid] = (s / WW) * 65536 + (s - (s / WW) * WW);
    }
    __syncthreads();

    auto issueA = [&](int ch) {
        int tap = ch >> 1, c0 = (ch & 1) * 64;
        int dy = tap / 3 - 1, dx = tap % 3 - 1;
        uint32_t aw = sb + OSM_A + (uint32_t)(ch & 1) * 16384u;
        #pragma unroll
        for (int r = 0; r < 4; r++) {
            int i = tid + r * 256;          // 0..1023 over 128 px x 8 segs
            int px = i >> 3, seg = i & 7;
            int yx = s_yx[px];
            int sy = (yx >> 16) + dy, sx = (yx & 0xFFFF) + dx;
            bool vld = ((unsigned)sy < (unsigned)HH) && ((unsigned)sx < (unsigned)WW);
            int syc = min(max(sy, 0), HH - 1), sxc = min(max(sx, 0), WW - 1);
            const char* src = (const char*)(xh + (size_t)(syc * WW + sxc) * CC + c0) + seg * 16;
            uint32_t dst = (aw + (uint32_t)px * 128u + (uint32_t)seg * 16u)
                           ^ ((uint32_t)(px & 7) << 4);
            cp16z(dst, src, vld ? 16u : 0u);
        }
        // B chunk: 4KB
        uint32_t bw = sb + OSM_B + (uint32_t)(ch & 1) * 4096u;
        const char* gb = (const char*)g_wom + (size_t)ch * 4096;
        cp16(bw + (uint32_t)tid * 16u, gb + (size_t)tid * 16);
        asm volatile("cp.async.commit_group;" ::: "memory");
    };

    // warp geometry: 4 M-quarters (32 px) x 2 N-halves (16 oc)
    int wm = wid & 3;
    int wn = wid >> 2;
    uint32_t rsel = lane & 15;
    uint32_t csel = (uint32_t)(lane >> 4) * 16u;
    uint32_t xorv = (rsel & 7) * 16u;
    uint32_t aLin = (uint32_t)(wm * 32 + rsel) * 128u + csel;
    uint32_t bLin = (uint32_t)(wn * 16 + rsel) * 128u + csel;

    float acc[16];
    #pragma unroll
    for (int i = 0; i < 16; i++) acc[i] = 0.f;

    issueA(0);
    for (int ch = 0; ch < NCH; ch++) {
        asm volatile("cp.async.wait_group 0;" ::: "memory");
        __syncthreads();
        if (ch + 1 < NCH) issueA(ch + 1);

        uint32_t aT = sb + OSM_A + (uint32_t)(ch & 1) * 16384u;
        uint32_t bT = sb + OSM_B + (uint32_t)(ch & 1) * 4096u;
        #pragma unroll
        for (int t = 0; t < 4; t++) {
            uint32_t aF[2][4], bF[4];
            #pragma unroll
            for (int mt = 0; mt < 2; mt++)
                ldsm4(aF[mt], (aT + aLin + (uint32_t)mt * 2048u + (uint32_t)t * 32u) ^ xorv);
            ldsm4(bF, (bT + bLin + (uint32_t)t * 32u) ^ xorv);
            mma16816h(&acc[0],  aF[0], bF[0], bF[2]);
            mma16816h(&acc[4],  aF[0], bF[1], bF[3]);
            mma16816h(&acc[8],  aF[1], bF[0], bF[2]);
            mma16816h(&acc[12], aF[1], bF[1], bF[3]);
        }
        __syncthreads();
    }

    // ---- stage accumulators: sEp[px][32 oc] ----
    float* sEp = (float*)(smem + OSM_EP);
    int r0 = lane >> 2, cl = (lane & 3) * 2;
    #pragma unroll
    for (int mt = 0; mt < 2; mt++) {
        #pragma unroll
        for (int n8 = 0; n8 < 2; n8++) {
            float* a4 = &acc[(mt * 2 + n8) * 4];
            int px = wm * 32 + mt * 16 + r0;
            int oc = wn * 16 + n8 * 8 + cl;
            sEp[px * 32 + oc]           = a4[0];
            sEp[px * 32 + oc + 1]       = a4[1];
            sEp[(px + 8) * 32 + oc]     = a4[2];
            sEp[(px + 8) * 32 + oc + 1] = a4[3];
        }
    }
    __syncthreads();

    // ---- meta epilogue: one thread per pixel ----
    if (tid < 128) {
        int yx = s_yx[tid];
        int y = yx >> 16, xq = yx & 0xFFFF;
        float a[27];
        #pragma unroll
        for (int oc = 0; oc < 18; oc++) a[oc] = sEp[tid * 32 + oc] + ob[oc];
        #pragma unroll
        for (int oc = 18; oc < 27; oc++) a[oc] = sEp[tid * 32 + oc] + mb[oc - 18];

        size_t pix = (size_t)b * SS + s0 + tid;
        #pragma unroll
        for (int k = 0; k < 9; k++) {
            int kh = k / 3, kw = k % 3;
            float py = (float)(y + kh - 1) + a[2 * k];
            float px_ = (float)(xq + kw - 1) + a[2 * k + 1];
            float m = 1.f / (1.f + __expf(-a[18 + k]));

            float y0f = floorf(py), x0f = floorf(px_);
            float wy1 = py - y0f, wx1 = px_ - x0f;
            float wy0 = 1.f - wy1, wx0 = 1.f - wx1;
            int y0 = (int)y0f, x0i = (int)x0f;
            int y1 = y0 + 1, x1 = x0i + 1;
            bool vy0 = (unsigned)y0  < (unsigned)HH;
            bool vy1 = (unsigned)y1  < (unsigned)HH;
            bool vx0 = (unsigned)x0i < (unsigned)WW;
            bool vx1 = (unsigned)x1  < (unsigned)WW;
            int cy0 = min(max(y0, 0), HH - 1), cy1 = min(max(y1, 0), HH - 1);
            int cx0 = min(max(x0i, 0), WW - 1), cx1 = min(max(x1, 0), WW - 1);

            float w00 = (vy0 && vx0) ? wy0 * wx0 * m : 0.f;
            float w01 = (vy0 && vx1) ? wy0 * wx1 * m : 0.f;
            float w10 = (vy1 && vx0) ? wy1 * wx0 * m : 0.f;
            float w11 = (vy1 && vx1) ? wy1 * wx1 * m : 0.f;

            g_mw[(size_t)k * BSS + pix] = make_float4(w00, w01, w10, w11);
            g_mi[(size_t)k * BSS + pix] = make_int4(cy0 * WW + cx0, cy0 * WW + cx1,
                                                    cy1 * WW + cx0, cy1 * WW + cx1);
        }
    }
}

// ---------------- kernel 2: deformable gather (fp16 src) + fp16 mma GEMM ----------------
// CTA: 64 px x 256 oc, 256 threads, 8 warps (2M x 4N), warp 32x64, 2 CTAs/SM.
// Software-pipelined: gather LDGs of chunk ch overlap MMA of chunk ch-1.
#define DSM_MW   0          // float4[9*64]
#define DSM_MI   9216       // int4[9*64]
#define DSM_A    18432      // 2 x 8192
#define DSM_B    34816      // 2 x 32768
#define DSM_EP   34816      // epilogue staging reuses B[0]
#define DSM_TOT  100352

__global__ __launch_bounds__(256, 2) void deform_mma_kernel(
    float* __restrict__ out, const float* __restrict__ bias)
{
    extern __shared__ char smem[];
    uint32_t sb = smem_u32(smem);
    int tid = threadIdx.x;
    int wid = tid >> 5;
    int lane = tid & 31;

    int tile = blockIdx.x;
    int b = tile / (SS / 64);
    int s0 = (tile - b * (SS / 64)) * 64;

    float4* s_mw4 = (float4*)(smem + DSM_MW);
    int4*   s_mi4 = (int4*)(smem + DSM_MI);

    // load ALL 9 taps' meta for this 64-px tile (one-time)
    for (int i = tid; i < 576; i += 256) {
        size_t mo = (size_t)(i >> 6) * BSS + (size_t)b * SS + s0 + (i & 63);
        s_mw4[i] = g_mw[mo];
        s_mi4[i] = g_mi[mo];
    }

    // prefetch B chunk 0 (32KB)
    {
        const char* gw = (const char*)g_wh;
        uint32_t dst = sb + DSM_B;
        #pragma unroll
        for (int i = 0; i < 8; i++) {
            uint32_t off = (uint32_t)(tid + i * 256) * 16u;
            cp16(dst + off, gw + off);
        }
        asm volatile("cp.async.commit_group;" ::: "memory");
    }
    __syncthreads();   // meta visible to all

    // warp geometry: 2 M-halves (32 px) x 4 N-quarters (64 oc)
    int wm = wid & 1;
    int wn = wid >> 1;
    uint32_t rsel = lane & 15;
    uint32_t csel = (uint32_t)(lane >> 4) * 16u;
    uint32_t xorv = (rsel & 7) * 16u;
    uint32_t aLin = (uint32_t)(wm * 32 + rsel) * 128u + csel;
    uint32_t bLin = (uint32_t)(wn * 64 + rsel) * 128u + csel;

    float acc[64];
    #pragma unroll
    for (int i = 0; i < 64; i++) acc[i] = 0.f;

    int g = tid >> 3, j = tid & 7;     // g: px group (2 px), j: 8-ch group
    const __half* xb = g_xh + (size_t)b * SS * CC;

    // half of the MMA work for chunk chm (2 of 4 ksteps)
    auto mma_half = [&](int chm, int h) {
        uint32_t aT = sb + DSM_A + (uint32_t)(chm & 1) * 8192u;
        uint32_t bT = sb + DSM_B + (uint32_t)(chm & 1) * 32768u;
        #pragma unroll
        for (int tt = 0; tt < 2; tt++) {
            int t = h * 2 + tt;
            uint32_t aF[2][4], bF[4][4];
            #pragma unroll
            for (int mt = 0; mt < 2; mt++)
                ldsm4(aF[mt], (aT + aLin + (uint32_t)mt * 2048u + (uint32_t)t * 32u) ^ xorv);
            #pragma unroll
            for (int ng = 0; ng < 4; ng++)
                ldsm4(bF[ng], (bT + bLin + (uint32_t)ng * 2048u + (uint32_t)t * 32u) ^ xorv);
            #pragma unroll
            for (int mt = 0; mt < 2; mt++) {
                #pragma unroll
                for (int ng = 0; ng < 4; ng++) {
                    mma16816h(&acc[(mt * 8 + ng * 2) * 4],     aF[mt], bF[ng][0], bF[ng][2]);
                    mma16816h(&acc[(mt * 8 + ng * 2 + 1) * 4], aF[mt], bF[ng][1], bF[ng][3]);
                }
            }
        }
    };

    for (int ch = 0; ch < NCH; ch++) {
        int tap = ch >> 1;
        int c0 = (ch & 1) * 64;
        uint32_t aw = sb + DSM_A + (uint32_t)(ch & 1) * 8192u;
        const __half* xc = xb + c0 + j * 8;

        #pragma unroll
        for (int it = 0; it < 2; it++) {
            int p = g + it * 32;
            float4 wv = s_mw4[tap * 64 + p];
            int4  iv = s_mi4[tap * 64 + p];
            // issue gather loads for (ch, sample it)
            uint4 ra = *(const uint4*)(xc + (size_t)iv.x * CC);
            uint4 rb = *(const uint4*)(xc + (size_t)iv.y * CC);
            uint4 rc = *(const uint4*)(xc + (size_t)iv.z * CC);
            uint4 rd = *(const uint4*)(xc + (size_t)iv.w * CC);

            // overlap the in-flight loads with half of MMA(ch-1)
            if (ch > 0) mma_half(ch - 1, it);

            uint32_t va[4] = {ra.x, ra.y, ra.z, ra.w};
            uint32_t vb[4] = {rb.x, rb.y, rb.z, rb.w};
            uint32_t vc[4] = {rc.x, rc.y, rc.z, rc.w};
            uint32_t vd[4] = {rd.x, rd.y, rd.z, rd.w};
            uint32_t hres[4];
            #pragma unroll
            for (int q = 0; q < 4; q++) {
                float2 fa = __half22float2(*reinterpret_cast<__half2*>(&va[q]));
                float2 fb = __half22float2(*reinterpret_cast<__half2*>(&vb[q]));
                float2 fc = __half22float2(*reinterpret_cast<__half2*>(&vc[q]));
                float2 fd = __half22float2(*reinterpret_cast<__half2*>(&vd[q]));
                float sx = wv.x * fa.x + wv.y * fb.x + wv.z * fc.x + wv.w * fd.x;
                float sy = wv.x * fa.y + wv.y * fb.y + wv.z * fc.y + wv.w * fd.y;
                hres[q] = pkh2(sx, sy);
            }
            uint32_t addr = (aw + (uint32_t)p * 128u + (uint32_t)j * 16u)
                            ^ ((uint32_t)(p & 7) << 4);
            asm volatile("st.shared.v4.b32 [%0], {%1,%2,%3,%4};"
                         :: "r"(addr), "r"(hres[0]), "r"(hres[1]),
                            "r"(hres[2]), "r"(hres[3]));
        }

        // B(ch) resident + all warps' STS(ch) and MMA(ch-1) complete
        asm volatile("cp.async.wait_group 0;" ::: "memory");
        __syncthreads();   // the ONLY barrier per chunk

        // prefetch B(ch+1) (safe: all warps past barrier => MMA(ch-1) done)
        if (ch + 1 < NCH) {
            const char* gw = (const char*)g_wh + (size_t)(ch + 1) * 32768;
            uint32_t dst = sb + DSM_B + (uint32_t)((ch + 1) & 1) * 32768u;
            #pragma unroll
            for (int i = 0; i < 8; i++) {
                uint32_t off = (uint32_t)(tid + i * 256) * 16u;
                cp16(dst + off, gw + off);
            }
            asm volatile("cp.async.commit_group;" ::: "memory");
        }
    }

    // drain: MMA for the last chunk
    mma_half(NCH - 1, 0);
    mma_half(NCH - 1, 1);
    __syncthreads();

    // ---- epilogue: stage 64-oc quarters in smem, coalesced store ----
    float* sEp = (float*)(smem + DSM_EP);
    int r0l = lane >> 2, c0l = (lane & 3) * 2;
    for (int q = 0; q < 4; q++) {
        if (wn == q) {
            #pragma unroll
            for (int mt = 0; mt < 2; mt++) {
                int px = wm * 32 + mt * 16 + r0l;
                #pragma unroll
                for (int nn = 0; nn < 8; nn++) {
                    float* a4 = &acc[(mt * 8 + nn) * 4];
                    int ocl = nn * 8 + c0l;
                    sEp[ocl * 68 + px]           = a4[0];
                    sEp[(ocl + 1) * 68 + px]     = a4[1];
                    sEp[ocl * 68 + px + 8]       = a4[2];
                    sEp[(ocl + 1) * 68 + px + 8] = a4[3];
                }
            }
        }
        __syncthreads();
        for (int i = tid; i < 1024; i += 256) {
            int r = i >> 4, c = i & 15;
            float4 v = *(float4*)(sEp + r * 68 + c * 4);
            float bv = __ldg(bias + q * 64 + r);
            v.x += bv; v.y += bv; v.z += bv; v.w += bv;
            *(float4*)(out + ((size_t)b * OO + q * 64 + r) * SS + s0 + c * 4) = v;
        }
        __syncthreads();
    }
}

// ---------------- launch ----------------
extern "C" void kernel_launch(void* const* d_in, const int* in_sizes, int n_in,
                              void* d_out, int out_size) {
    const float* x    = (const float*)d_in[0];
    const float* ow   = (const float*)d_in[1];
    const float* ob   = (const float*)d_in[2];
    const float* mw   = (const float*)d_in[3];
    const float* mb   = (const float*)d_in[4];
    const float* w    = (const float*)d_in[5];
    const float* bias = (const float*)d_in[6];
    float* out = (float*)d_out;

    transpose_x_kernel<<<dim3(SS / 32, CC / 32, BB), dim3(32, 8)>>>(x);
    wprep_kernel<<<dim3(OO, NCH), 64>>>(w);
    owprep_kernel<<<dim3(32, NCH), 64>>>(ow, mw);

    cudaFuncSetAttribute(offmask_mma_kernel,
                         cudaFuncAttributeMaxDynamicSharedMemorySize, OSM_TOT);
    offmask_mma_kernel<<<BSS / 128, 256, OSM_TOT>>>(ob, mb);

    cudaFuncSetAttribute(deform_mma_kernel,
                         cudaFuncAttributeMaxDynamicSharedMemorySize, DSM_TOT);
    deform_mma_kernel<<<BSS / 64, 256, DSM_TOT>>>(out, bias);
}